// round 1
// baseline (speedup 1.0000x reference)
#include <cuda_runtime.h>
#include <cstdint>

// VariableGroupNorm: x[N,C,H,W] fp32, ragged groups (channels contiguous per group),
// per-(n,g) mean/var -> y = x*scale + shift.
// N=32, C=256, H=W=56, G=32. Group data per (n,g) is fully contiguous: gs*H*W floats.

#define NB 32
#define CC 256
#define HH 56
#define WW 56
#define GG 32
#define HW (HH * WW)          // 3136
#define HW4 (HW / 4)          // 784 float4 per channel
#define VGN_EPS 1e-5f
#define TPB 256

__device__ int d_gstart[GG];   // first channel of group g
__device__ int d_gsize[GG];    // channels in group g
__device__ int d_gorder[GG];   // groups sorted big-first (scheduling order)

// Tiny setup: decode group_sizes (int32 or int64, defensively), prefix sums,
// and a big-groups-first execution order for load balance.
__global__ void vgn_setup_kernel(const void* __restrict__ gs_raw) {
    int sz[GG];
    const int* p32 = (const int*)gs_raw;
    long long sum32 = 0;
    for (int i = 0; i < GG; i++) sum32 += p32[i];
    if (sum32 == (long long)CC) {
        for (int i = 0; i < GG; i++) sz[i] = p32[i];
    } else {
        const long long* p64 = (const long long*)gs_raw;
        for (int i = 0; i < GG; i++) sz[i] = (int)p64[i];
    }
    int start = 0;
    for (int i = 0; i < GG; i++) {
        d_gstart[i] = start;
        d_gsize[i]  = sz[i];
        start += sz[i];
    }
    // Big groups first so the long blocks launch in the first waves.
    const int avg = start / GG;
    int idx = 0;
    for (int i = 0; i < GG; i++) if (sz[i] >  avg) d_gorder[idx++] = i;
    for (int i = 0; i < GG; i++) if (sz[i] <= avg) d_gorder[idx++] = i;
}

__global__ void __launch_bounds__(TPB)
vgn_kernel(const float* __restrict__ x,
           const float* __restrict__ gamma,
           const float* __restrict__ beta,
           float* __restrict__ out) {
    const int item = blockIdx.x;             // 0 .. N*G-1
    const int n  = item & (NB - 1);          // n fastest: a big group spreads over N blocks
    const int g  = d_gorder[item / NB];
    const int c0 = d_gstart[g];
    const int gs = d_gsize[g];

    const size_t base = ((size_t)n * CC + (size_t)c0) * HW;
    const float4* __restrict__ px = (const float4*)(x + base);
    float4* __restrict__ po       = (float4*)(out + base);
    const int nv = gs * HW4;                 // float4 count for this group

    // ---- pass 1: sum / sumsq ----
    float s = 0.f, ss = 0.f;
    #pragma unroll 4
    for (int i = threadIdx.x; i < nv; i += TPB) {
        const float4 v = px[i];
        s  += (v.x + v.y) + (v.z + v.w);
        ss += v.x * v.x + v.y * v.y + v.z * v.z + v.w * v.w;
    }

    // block reduce (8 warps)
    #pragma unroll
    for (int o = 16; o > 0; o >>= 1) {
        s  += __shfl_xor_sync(0xFFFFFFFFu, s,  o);
        ss += __shfl_xor_sync(0xFFFFFFFFu, ss, o);
    }
    __shared__ float shs[8], shss[8];
    __shared__ float sh_param[2];
    const int wid = threadIdx.x >> 5, lid = threadIdx.x & 31;
    if (lid == 0) { shs[wid] = s; shss[wid] = ss; }
    __syncthreads();
    if (threadIdx.x == 0) {
        float ts = 0.f, tss = 0.f;
        #pragma unroll
        for (int w = 0; w < 8; w++) { ts += shs[w]; tss += shss[w]; }
        const float inv   = 1.0f / (float)(gs * HW);
        const float mean  = ts * inv;
        const float var   = tss * inv - mean * mean;
        const float scale = gamma[g] * rsqrtf(var + VGN_EPS);
        sh_param[0] = scale;
        sh_param[1] = fmaf(-mean, scale, beta[g]);
    }
    __syncthreads();
    const float sc = sh_param[0];
    const float sf = sh_param[1];

    // ---- pass 2: normalize. Reads should hit L2 (just streamed by pass 1);
    // mark reads last-use and stores evict-first so output doesn't thrash L2. ----
    #pragma unroll 4
    for (int i = threadIdx.x; i < nv; i += TPB) {
        float4 v = __ldcs(px + i);
        v.x = fmaf(v.x, sc, sf);
        v.y = fmaf(v.y, sc, sf);
        v.z = fmaf(v.z, sc, sf);
        v.w = fmaf(v.w, sc, sf);
        __stcs(po + i, v);
    }
}

extern "C" void kernel_launch(void* const* d_in, const int* in_sizes, int n_in,
                              void* d_out, int out_size) {
    const float* x     = (const float*)d_in[0];
    const float* gamma = (const float*)d_in[1];
    const float* beta  = (const float*)d_in[2];
    const void*  gsz   = d_in[3];
    float* out = (float*)d_out;

    vgn_setup_kernel<<<1, 1>>>(gsz);
    vgn_kernel<<<NB * GG, TPB>>>(x, gamma, beta, out);
}

// round 2
// speedup vs baseline: 1.1316x; 1.1316x over previous
#include <cuda_runtime.h>
#include <cstdint>

// VariableGroupNorm: x[N,C,H,W] fp32, ragged groups (channels contiguous per group),
// per-(n,g) mean/var -> y = x*scale + shift.
// N=32, C=256, H=W=56, G=32. Group data per (n,g) is contiguous: gs*H*W floats.

#define NB 32
#define CC 256
#define GG 32
#define HW 3136               // 56*56
#define HW4 784               // float4 per channel
#define VGN_EPS 1e-5f
#define TPB 256

// Decode this block's group start/size from the raw group_sizes buffer.
// Defensive dtype handling: int32 if the 32 int32 reads sum to C, else int64.
// All CTAs read the same 128/256 bytes -> L1/L2 broadcast, negligible cost.
__device__ __forceinline__ void decode_group(const void* __restrict__ gs_raw,
                                             int g, int& c0, int& gs) {
    const int* p32 = (const int*)gs_raw;
    long long s32 = 0;
    #pragma unroll
    for (int i = 0; i < GG; i++) s32 += __ldg(&p32[i]);
    int start = 0, size = 0;
    if (s32 == (long long)CC) {
        #pragma unroll
        for (int i = 0; i < GG; i++) {
            int v = __ldg(&p32[i]);
            if (i < g) start += v;
            if (i == g) size = v;
        }
    } else {
        const long long* p64 = (const long long*)gs_raw;
        #pragma unroll
        for (int i = 0; i < GG; i++) {
            int v = (int)__ldg(&p64[i]);
            if (i < g) start += v;
            if (i == g) size = v;
        }
    }
    c0 = start;
    gs = size;
}

__global__ void __launch_bounds__(TPB)
vgn_kernel(const float* __restrict__ x,
           const float* __restrict__ gamma,
           const float* __restrict__ beta,
           float* __restrict__ out,
           const void* __restrict__ gs_raw) {
    const int item = blockIdx.x;             // 0 .. N*G-1
    const int n  = item & (NB - 1);          // n fastest: a group spreads over N blocks
    const int g  = item >> 5;                // natural order; CLC RR interleaves big/small
    int c0, gs;
    decode_group(gs_raw, g, c0, gs);

    const size_t base = ((size_t)n * CC + (size_t)c0) * HW;
    const float4* __restrict__ px = (const float4*)(x + base);
    float4* __restrict__ po       = (float4*)(out + base);
    const int nv = gs * HW4;                 // float4 count for this group

    // ---- pass 1: sum / sumsq, 8-wide batched loads for MLP ----
    float s = 0.f, ss = 0.f;
    int i = threadIdx.x;
    for (; i + 7 * TPB < nv; i += 8 * TPB) {
        float4 v[8];
        #pragma unroll
        for (int u = 0; u < 8; u++) v[u] = px[i + u * TPB];
        #pragma unroll
        for (int u = 0; u < 8; u++) {
            s  += (v[u].x + v[u].y) + (v[u].z + v[u].w);
            ss += v[u].x * v[u].x + v[u].y * v[u].y
                + v[u].z * v[u].z + v[u].w * v[u].w;
        }
    }
    for (; i < nv; i += TPB) {
        const float4 v = px[i];
        s  += (v.x + v.y) + (v.z + v.w);
        ss += v.x * v.x + v.y * v.y + v.z * v.z + v.w * v.w;
    }

    // block reduce (8 warps)
    #pragma unroll
    for (int o = 16; o > 0; o >>= 1) {
        s  += __shfl_xor_sync(0xFFFFFFFFu, s,  o);
        ss += __shfl_xor_sync(0xFFFFFFFFu, ss, o);
    }
    __shared__ float shs[8], shss[8];
    __shared__ float sh_param[2];
    const int wid = threadIdx.x >> 5, lid = threadIdx.x & 31;
    if (lid == 0) { shs[wid] = s; shss[wid] = ss; }
    __syncthreads();
    if (threadIdx.x == 0) {
        float ts = 0.f, tss = 0.f;
        #pragma unroll
        for (int w = 0; w < 8; w++) { ts += shs[w]; tss += shss[w]; }
        const float inv   = 1.0f / (float)(gs * HW);
        const float mean  = ts * inv;
        const float var   = tss * inv - mean * mean;
        const float scale = __ldg(&gamma[g]) * rsqrtf(var + VGN_EPS);
        sh_param[0] = scale;
        sh_param[1] = fmaf(-mean, scale, __ldg(&beta[g]));
    }
    __syncthreads();
    const float sc = sh_param[0];
    const float sf = sh_param[1];

    // ---- pass 2: normalize. Reads should hit L2 (just streamed by pass 1);
    // last-use reads + evict-first stores keep the output from thrashing L2. ----
    i = threadIdx.x;
    for (; i + 7 * TPB < nv; i += 8 * TPB) {
        float4 v[8];
        #pragma unroll
        for (int u = 0; u < 8; u++) v[u] = __ldcs(px + i + u * TPB);
        #pragma unroll
        for (int u = 0; u < 8; u++) {
            v[u].x = fmaf(v[u].x, sc, sf);
            v[u].y = fmaf(v[u].y, sc, sf);
            v[u].z = fmaf(v[u].z, sc, sf);
            v[u].w = fmaf(v[u].w, sc, sf);
            __stcs(po + i + u * TPB, v[u]);
        }
    }
    for (; i < nv; i += TPB) {
        float4 v = __ldcs(px + i);
        v.x = fmaf(v.x, sc, sf);
        v.y = fmaf(v.y, sc, sf);
        v.z = fmaf(v.z, sc, sf);
        v.w = fmaf(v.w, sc, sf);
        __stcs(po + i, v);
    }
}

extern "C" void kernel_launch(void* const* d_in, const int* in_sizes, int n_in,
                              void* d_out, int out_size) {
    const float* x     = (const float*)d_in[0];
    const float* gamma = (const float*)d_in[1];
    const float* beta  = (const float*)d_in[2];
    const void*  gsz   = d_in[3];
    float* out = (float*)d_out;

    vgn_kernel<<<NB * GG, TPB>>>(x, gamma, beta, out, gsz);
}